// round 3
// baseline (speedup 1.0000x reference)
#include <cuda_runtime.h>
#include <cuda_bf16.h>
#include <cstdint>

// ============================================================================
// TNLayer via HMMA (mma.sync m16n8k16 bf16) — tcgen05 unavailable because the
// harness compiles through compute_103 (non-'a') PTX.
//
// Per 64-sample tile:  D[64,112] = A[64,64] @ B[112,64]^T
//   A row n  = [x0 | x1] bf16, K padded 56->64 (zeros)
//   B row  0..9   = t0^T   (k = 0..27)
//   B row 10..109 = t1 flat (b*10+o) over k = 28..55
//   B rows 110,111 + all pads = 0
// Epilogue: c[n,o] = sum_b D[n,b] * D[n,10+b*10+o] + bias[o]; sigmoid.
// ============================================================================

#define NTHREADS  128
#define TILE_M    64
#define NTILES    16384          // 1048576 / 64
#define GRID_X    592            // 148 SMs * 4 persistent CTAs

#define A_STRIDE  144            // bytes per A row (72 bf16) -> conflict-free frags
#define B_STRIDE  144            // bytes per B row
#define D_STRIDE  113            // floats per D row (odd -> conflict-free epilogue)

#define OFF_A     0
#define OFF_B     (TILE_M * A_STRIDE)                 // 9216
#define OFF_D     (OFF_B + 112 * B_STRIDE)            // 25344
#define SMEM_BYTES (OFF_D + TILE_M * D_STRIDE * 4)    // 54272

static __device__ __forceinline__ void mma_bf16(float& c0, float& c1, float& c2, float& c3,
                                                uint32_t a0, uint32_t a1, uint32_t a2, uint32_t a3,
                                                uint32_t b0, uint32_t b1) {
    asm volatile(
        "mma.sync.aligned.m16n8k16.row.col.f32.bf16.bf16.f32 "
        "{%0,%1,%2,%3}, {%4,%5,%6,%7}, {%8,%9}, {%0,%1,%2,%3};"
        : "+f"(c0), "+f"(c1), "+f"(c2), "+f"(c3)
        : "r"(a0), "r"(a1), "r"(a2), "r"(a3), "r"(b0), "r"(b1));
}

__global__ void __launch_bounds__(NTHREADS, 4)
tn_kernel(const float* __restrict__ x,
          const float* __restrict__ t0,
          const float* __restrict__ t1,
          const float* __restrict__ bias,
          float* __restrict__ out)
{
    extern __shared__ uint8_t smem[];
    uint8_t* sA = smem + OFF_A;
    uint8_t* sB = smem + OFF_B;
    float*   sD = (float*)(smem + OFF_D);

    const int tid  = threadIdx.x;
    const int lane = tid & 31;
    const int w    = tid >> 5;
    const int g    = lane >> 2;     // group id (0..7)
    const int t    = lane & 3;      // thread-in-group (0..3)
    const int r0   = w * 16;        // this warp's m-tile base row

    // ---------------- one-time setup per CTA ----------------
    // zero all of B (weights region incl. pads)
    for (int i = tid; i < (112 * B_STRIDE) / 4; i += NTHREADS)
        ((uint32_t*)sB)[i] = 0u;
    // zero A's K-pad (cols 56..71 bf16 = bytes 112..143 of each row) — persists
    {
        int row = tid >> 1, half = tid & 1;
        *(uint4*)(sA + row * A_STRIDE + 112 + half * 16) = make_uint4(0u, 0u, 0u, 0u);
    }
    __syncthreads();

    // B rows 0..9: t0^T   B[b][k=i] = t0[i*10 + b]
    for (int idx = tid; idx < 280; idx += NTHREADS) {
        int i = idx / 10, b = idx % 10;
        *(__nv_bfloat16*)(sB + b * B_STRIDE + i * 2) = __float2bfloat16(t0[idx]);
    }
    // B rows 10..109: t1   B[10+f][k=28+j] = t1[j*100 + f]
    for (int idx = tid; idx < 2800; idx += NTHREADS) {
        int j = idx / 100, f = idx % 100;
        *(__nv_bfloat16*)(sB + (10 + f) * B_STRIDE + (28 + j) * 2) = __float2bfloat16(t1[idx]);
    }

    float biasr[5];
    {
        int p = tid & 1;
#pragma unroll
        for (int u = 0; u < 5; u++) biasr[u] = __ldg(bias + p * 5 + u);
    }
    __syncthreads();

    // ---------------- tile loop ----------------
    for (int tile = blockIdx.x; tile < NTILES; tile += gridDim.x) {
        // ---- load x tile: 64 samples * 56 f32 = 896 float4, coalesced ----
        const float4* src = (const float4*)x + (size_t)tile * 896;
#pragma unroll
        for (int i = 0; i < 7; i++) {
            int idx  = tid + i * NTHREADS;       // 0..895
            float4 v = src[idx];
            int row  = idx / 14;
            int col4 = idx % 14;                 // group of 4 k-values
            __nv_bfloat162 p0 = __floats2bfloat162_rn(v.x, v.y);
            __nv_bfloat162 p1 = __floats2bfloat162_rn(v.z, v.w);
            uint2 pk;
            pk.x = *reinterpret_cast<uint32_t*>(&p0);
            pk.y = *reinterpret_cast<uint32_t*>(&p1);
            *(uint2*)(sA + row * A_STRIDE + col4 * 8) = pk;
        }
        __syncthreads();

        // ---- GEMM: each warp does its 16-row m-tile over N=112, K=64 ----
        // A fragments for all 4 k-blocks (conflict-free: bank = 4g+t)
        uint32_t afr[4][4];
#pragma unroll
        for (int kb = 0; kb < 4; kb++) {
            const uint8_t* base = sA + kb * 32 + t * 4;
            afr[kb][0] = *(const uint32_t*)(base + (r0 + g) * A_STRIDE);
            afr[kb][1] = *(const uint32_t*)(base + (r0 + g + 8) * A_STRIDE);
            afr[kb][2] = *(const uint32_t*)(base + (r0 + g) * A_STRIDE + 16);
            afr[kb][3] = *(const uint32_t*)(base + (r0 + g + 8) * A_STRIDE + 16);
        }

#pragma unroll
        for (int nb = 0; nb < 14; nb++) {
            float c0 = 0.f, c1 = 0.f, c2 = 0.f, c3 = 0.f;
            const uint8_t* brow = sB + (nb * 8 + g) * B_STRIDE + t * 4;
#pragma unroll
            for (int kb = 0; kb < 4; kb++) {
                uint32_t b0 = *(const uint32_t*)(brow + kb * 32);
                uint32_t b1 = *(const uint32_t*)(brow + kb * 32 + 16);
                mma_bf16(c0, c1, c2, c3,
                         afr[kb][0], afr[kb][1], afr[kb][2], afr[kb][3], b0, b1);
            }
            // store D fragment: rows r0+g / r0+g+8, cols nb*8 + 2t (+1)
            float* d0 = sD + (r0 + g) * D_STRIDE + nb * 8 + 2 * t;
            float* d1 = sD + (r0 + g + 8) * D_STRIDE + nb * 8 + 2 * t;
            d0[0] = c0; d0[1] = c1;
            d1[0] = c2; d1[1] = c3;
        }
        __syncthreads();

        // ---- epilogue: 2 threads per sample, 5 outputs each ----
        {
            int s = tid >> 1, p = tid & 1;
            const float* drow = sD + s * D_STRIDE;
            float h0[10];
#pragma unroll
            for (int b = 0; b < 10; b++) h0[b] = drow[b];
            float c[5];
#pragma unroll
            for (int u = 0; u < 5; u++) c[u] = biasr[u];
            const float* h1 = drow + 10 + p * 5;
#pragma unroll
            for (int b = 0; b < 10; b++) {
#pragma unroll
                for (int u = 0; u < 5; u++)
                    c[u] = fmaf(h0[b], h1[b * 10 + u], c[u]);
            }
            float* outp = out + (size_t)tile * (TILE_M * 10) + s * 10 + p * 5;
#pragma unroll
            for (int u = 0; u < 5; u++)
                outp[u] = __fdividef(1.0f, 1.0f + __expf(-c[u]));
        }
        __syncthreads();   // protect sA / sD before next tile overwrites them
    }
}

extern "C" void kernel_launch(void* const* d_in, const int* in_sizes, int n_in,
                              void* d_out, int out_size) {
    const float* x    = (const float*)d_in[0];
    const float* t0   = (const float*)d_in[1];
    const float* t1   = (const float*)d_in[2];
    const float* bias = (const float*)d_in[3];
    float* out = (float*)d_out;

    cudaFuncSetAttribute(tn_kernel, cudaFuncAttributeMaxDynamicSharedMemorySize,
                         SMEM_BYTES);
    tn_kernel<<<GRID_X, NTHREADS, SMEM_BYTES>>>(x, t0, t1, bias, out);
}

// round 4
// speedup vs baseline: 2.3566x; 2.3566x over previous
#include <cuda_runtime.h>
#include <cuda_bf16.h>
#include <cstdint>

// ============================================================================
// TNLayer, round 4: split GEMMs + N-permuted h1 layout -> thread-local epilogue
//
//  h0[n,b]   = sum_i x0[n,i] t0[i,b]              (GEMM1: N=16, K=32)
//  h1[n,b,o] = sum_j x1[n,j] t1[j,b,o]            (GEMM2: N=104, K=32)
//  c[n,o]    = sum_b h0 * h1 + bias[o]; sigmoid
//
// h1 B column layout (N-permutation):
//   cols  8b + o       (b=0..9, o=0..7)   "even blocks" e=b
//   cols 80 + 8q + c   (q=0..2, c=2t'+j -> b=4q+t', o=8+j)  "o89 blocks"
// => accumulator c0/c1 of thread t = o in {2t,2t+1} for ALL b: epilogue is
//    thread-local FMAs. Only o=8,9 need a quad bfly reduce.
// h0 distributed to the quad with width-4 shuffles (no shared memory).
// A tiles double-buffered via cp.async (f32 in smem; cvt to bf16 at frag load).
// ============================================================================

#define NTHREADS 128
#define TILE_M   64
#define NTILES   16384            // 1048576 / 64
#define GRID_X   592              // 148 SMs * 4 CTAs

#define A_STRIDE 288              // bytes per A row (72 f32); 288 % 128 == 32 -> LDS.64 conflict-free
#define B_STRIDE 80               // bytes per B row (40 bf16); 80/4=20 -> bank-bijective frags

#define OFF_A0   0
#define OFF_A1   (64 * A_STRIDE)              // 18432
#define OFF_B0   (2 * 64 * A_STRIDE)          // 36864 (16 rows)
#define OFF_B1   (OFF_B0 + 16 * B_STRIDE)     // 38144 (104 rows)
#define SMEM_BYTES (OFF_B1 + 104 * B_STRIDE)  // 46464

static __device__ __forceinline__ uint32_t smem_u32(const void* p) {
    uint32_t a;
    asm("{ .reg .u64 t; cvta.to.shared.u64 t, %1; cvt.u32.u64 %0, t; }"
        : "=r"(a) : "l"(p));
    return a;
}
static __device__ __forceinline__ void cp_async16(uint32_t dst, const void* src) {
    asm volatile("cp.async.cg.shared.global [%0], [%1], 16;" :: "r"(dst), "l"(src));
}
static __device__ __forceinline__ void cp_commit() {
    asm volatile("cp.async.commit_group;" ::: "memory");
}
template <int N> static __device__ __forceinline__ void cp_wait() {
    asm volatile("cp.async.wait_group %0;" :: "n"(N) : "memory");
}
static __device__ __forceinline__ void mma_bf16(float& c0, float& c1, float& c2, float& c3,
                                                uint32_t a0, uint32_t a1, uint32_t a2, uint32_t a3,
                                                uint32_t b0, uint32_t b1) {
    asm volatile(
        "mma.sync.aligned.m16n8k16.row.col.f32.bf16.bf16.f32 "
        "{%0,%1,%2,%3}, {%4,%5,%6,%7}, {%8,%9}, {%0,%1,%2,%3};"
        : "+f"(c0), "+f"(c1), "+f"(c2), "+f"(c3)
        : "r"(a0), "r"(a1), "r"(a2), "r"(a3), "r"(b0), "r"(b1));
}
static __device__ __forceinline__ uint32_t packbf(float lo, float hi) {
    __nv_bfloat162 p = __floats2bfloat162_rn(lo, hi);
    return *reinterpret_cast<uint32_t*>(&p);
}
static __device__ __forceinline__ float sigmoidf_(float c) {
    return __fdividef(1.0f, 1.0f + __expf(-c));
}

__global__ void __launch_bounds__(NTHREADS, 4)
tn_kernel(const float* __restrict__ x,
          const float* __restrict__ t0,
          const float* __restrict__ t1,
          const float* __restrict__ bias,
          float* __restrict__ out)
{
    extern __shared__ uint8_t smem[];
    const uint32_t smem_u = smem_u32(smem);
    const int tid  = threadIdx.x;
    const int lane = tid & 31;
    const int w    = tid >> 5;
    const int g    = lane >> 2;
    const int t    = lane & 3;
    const int r0   = w * 16;

    // ---------------- one-time setup ----------------
    // zero all B rows (incl. pad/invalid)
    for (int i = tid; i < (16 * B_STRIDE + 104 * B_STRIDE) / 4; i += NTHREADS)
        ((uint32_t*)(smem + OFF_B0))[i] = 0u;
    // zero A pad cols 56..71 in both buffers (cp.async never writes there)
    for (int i = tid; i < 2 * 64 * 16; i += NTHREADS) {
        int b = i >> 10, r = (i >> 4) & 63, c = i & 15;
        *(float*)(smem + b * OFF_A1 + r * A_STRIDE + (56 + c) * 4) = 0.0f;
    }
    __syncthreads();
    // B0 rows 0..9: B0[b][k=i] = t0[i,b]
    for (int idx = tid; idx < 280; idx += NTHREADS) {
        int i = idx / 10, b = idx % 10;
        *(__nv_bfloat16*)(smem + OFF_B0 + b * B_STRIDE + i * 2) =
            __float2bfloat16(t0[idx]);
    }
    // B1 even blocks: row 8b+o, k=j  (o = 0..7)
    for (int idx = tid; idx < 2240; idx += NTHREADS) {
        int j = idx / 80, r = idx % 80, b = r >> 3, o = r & 7;
        *(__nv_bfloat16*)(smem + OFF_B1 + (b * 8 + o) * B_STRIDE + j * 2) =
            __float2bfloat16(t1[j * 100 + b * 10 + o]);
    }
    // B1 o89 blocks: row 80+8q+c, c=2t'+jj -> b=4q+t', o=8+jj
    for (int idx = tid; idx < 672; idx += NTHREADS) {
        int j = idx / 24, r = idx % 24, q = r >> 3, c = r & 7;
        int b = 4 * q + (c >> 1);
        if (b < 10)
            *(__nv_bfloat16*)(smem + OFF_B1 + (80 + q * 8 + c) * B_STRIDE + j * 2) =
                __float2bfloat16(t1[j * 100 + b * 10 + 8 + (c & 1)]);
    }
    const float bs0 = __ldg(bias + 2 * t);
    const float bs1 = __ldg(bias + 2 * t + 1);
    const float bs8 = __ldg(bias + 8);
    const float bs9 = __ldg(bias + 9);
    __syncthreads();

    // ---------------- pipelined tile loop ----------------
    auto prefetch = [&](int tl, int buf) {
        const float4* src = (const float4*)x + (size_t)tl * 896;
        uint32_t sa = smem_u + (buf ? OFF_A1 : OFF_A0);
#pragma unroll
        for (int i = 0; i < 7; i++) {
            int idx = tid + i * NTHREADS;
            int row = idx / 14, c4 = idx % 14;
            cp_async16(sa + row * A_STRIDE + c4 * 16, src + idx);
        }
        cp_commit();
    };

    int tile = blockIdx.x;
    prefetch(tile, 0);
    int buf = 0;

    for (; tile < NTILES; tile += GRID_X) {
        int nt = tile + GRID_X;
        if (nt < NTILES) { prefetch(nt, buf ^ 1); cp_wait<1>(); }
        else             { cp_wait<0>(); }
        __syncthreads();

        const float* Ag = (const float*)(smem + (buf ? OFF_A1 : OFF_A0)
                                         + (size_t)(r0 + g) * A_STRIDE);
        const float* Ah = (const float*)((const uint8_t*)Ag + 8 * A_STRIDE);

        // ---- GEMM1: h0 (N=16, K=32), and preload h1 A frags ----
        float e00 = 0, e01 = 0, e02 = 0, e03 = 0;   // cols 0..7  (b = 2t, 2t+1)
        float f00 = 0, f01 = 0, f02 = 0, f03 = 0;   // cols 8..15 (b = 8+2t)
        uint32_t xa[2][4];                           // h1 A frags, reused
#pragma unroll
        for (int kb = 0; kb < 2; kb++) {
            const int k0 = 2 * t + 16 * kb;
            float2 vg0 = *(const float2*)(Ag + k0);
            float2 vh0 = *(const float2*)(Ah + k0);
            float2 vg1 = *(const float2*)(Ag + k0 + 8);
            float2 vh1 = *(const float2*)(Ah + k0 + 8);
            uint32_t a0 = packbf(vg0.x, vg0.y);
            uint32_t a1 = packbf(vh0.x, vh0.y);
            uint32_t a2 = packbf(vg1.x, vg1.y);
            uint32_t a3 = packbf(vh1.x, vh1.y);
            const uint8_t* br = smem + OFF_B0 + g * B_STRIDE + t * 4 + kb * 32;
            mma_bf16(e00, e01, e02, e03, a0, a1, a2, a3,
                     *(const uint32_t*)br, *(const uint32_t*)(br + 16));
            const uint8_t* br2 = br + 8 * B_STRIDE;
            mma_bf16(f00, f01, f02, f03, a0, a1, a2, a3,
                     *(const uint32_t*)br2, *(const uint32_t*)(br2 + 16));
            // h1 A frags: x1 lives at cols 28..55 (+pad)
            const int k1 = k0 + 28;
            float2 wg0 = *(const float2*)(Ag + k1);
            float2 wh0 = *(const float2*)(Ah + k1);
            float2 wg1 = *(const float2*)(Ag + k1 + 8);
            float2 wh1 = *(const float2*)(Ah + k1 + 8);
            xa[kb][0] = packbf(wg0.x, wg0.y);
            xa[kb][1] = packbf(wh0.x, wh0.y);
            xa[kb][2] = packbf(wg1.x, wg1.y);
            xa[kb][3] = packbf(wh1.x, wh1.y);
        }

        // ---- broadcast h0 across the quad (width-4 shuffles) ----
        float h0g[10], h0h[10];
#pragma unroll
        for (int u = 0; u < 4; u++) {
            h0g[2 * u]     = __shfl_sync(0xffffffffu, e00, u, 4);
            h0g[2 * u + 1] = __shfl_sync(0xffffffffu, e01, u, 4);
            h0h[2 * u]     = __shfl_sync(0xffffffffu, e02, u, 4);
            h0h[2 * u + 1] = __shfl_sync(0xffffffffu, e03, u, 4);
        }
        h0g[8] = __shfl_sync(0xffffffffu, f00, 0, 4);
        h0g[9] = __shfl_sync(0xffffffffu, f01, 0, 4);
        h0h[8] = __shfl_sync(0xffffffffu, f02, 0, 4);
        h0h[9] = __shfl_sync(0xffffffffu, f03, 0, 4);

        // ---- GEMM2 even blocks + thread-local contraction ----
        float pA0g = 0, pA1g = 0, pA0h = 0, pA1h = 0;   // o = 2t, 2t+1
#pragma unroll
        for (int e = 0; e < 10; e++) {
            float c0 = 0, c1 = 0, c2 = 0, c3 = 0;
#pragma unroll
            for (int kb = 0; kb < 2; kb++) {
                const uint8_t* br = smem + OFF_B1 + (e * 8 + g) * B_STRIDE
                                    + t * 4 + kb * 32;
                mma_bf16(c0, c1, c2, c3,
                         xa[kb][0], xa[kb][1], xa[kb][2], xa[kb][3],
                         *(const uint32_t*)br, *(const uint32_t*)(br + 16));
            }
            pA0g = fmaf(h0g[e], c0, pA0g);
            pA1g = fmaf(h0g[e], c1, pA1g);
            pA0h = fmaf(h0h[e], c2, pA0h);
            pA1h = fmaf(h0h[e], c3, pA1h);
        }

        // ---- GEMM2 o89 blocks: b = 4q + t, quad-reduced ----
        float p8g = 0, p9g = 0, p8h = 0, p9h = 0;
#pragma unroll
        for (int q = 0; q < 3; q++) {
            float c0 = 0, c1 = 0, c2 = 0, c3 = 0;
#pragma unroll
            for (int kb = 0; kb < 2; kb++) {
                const uint8_t* br = smem + OFF_B1 + (80 + q * 8 + g) * B_STRIDE
                                    + t * 4 + kb * 32;
                mma_bf16(c0, c1, c2, c3,
                         xa[kb][0], xa[kb][1], xa[kb][2], xa[kb][3],
                         *(const uint32_t*)br, *(const uint32_t*)(br + 16));
            }
            // fetch h0[4q+t] from pre-broadcast owners (b>=10 -> acc==0, harmless)
            int srcl = 2 * q + (t >> 1);
            float v0 = __shfl_sync(0xffffffffu, e00, srcl, 4);
            float v1 = __shfl_sync(0xffffffffu, e01, srcl, 4);
            float v2 = __shfl_sync(0xffffffffu, e02, srcl, 4);
            float v3 = __shfl_sync(0xffffffffu, e03, srcl, 4);
            float vg = (t & 1) ? v1 : v0;
            float vh = (t & 1) ? v3 : v2;
            p8g = fmaf(vg, c0, p8g);
            p9g = fmaf(vg, c1, p9g);
            p8h = fmaf(vh, c2, p8h);
            p9h = fmaf(vh, c3, p9h);
        }
        p8g += __shfl_xor_sync(0xffffffffu, p8g, 1);
        p8g += __shfl_xor_sync(0xffffffffu, p8g, 2);
        p9g += __shfl_xor_sync(0xffffffffu, p9g, 1);
        p9g += __shfl_xor_sync(0xffffffffu, p9g, 2);
        p8h += __shfl_xor_sync(0xffffffffu, p8h, 1);
        p8h += __shfl_xor_sync(0xffffffffu, p8h, 2);
        p9h += __shfl_xor_sync(0xffffffffu, p9h, 1);
        p9h += __shfl_xor_sync(0xffffffffu, p9h, 2);

        // ---- sigmoid + store ----
        float* og = out + ((size_t)tile * 64 + r0 + g) * 10;
        float2 sg = make_float2(sigmoidf_(pA0g + bs0), sigmoidf_(pA1g + bs1));
        float2 sh = make_float2(sigmoidf_(pA0h + bs0), sigmoidf_(pA1h + bs1));
        *(float2*)(og + 2 * t)      = sg;
        *(float2*)(og + 80 + 2 * t) = sh;
        if (t == 0) {
            *(float2*)(og + 8)  = make_float2(sigmoidf_(p8g + bs8), sigmoidf_(p9g + bs9));
            *(float2*)(og + 88) = make_float2(sigmoidf_(p8h + bs8), sigmoidf_(p9h + bs9));
        }

        __syncthreads();   // all warps done with buf before it is refilled
        buf ^= 1;
    }
}

extern "C" void kernel_launch(void* const* d_in, const int* in_sizes, int n_in,
                              void* d_out, int out_size) {
    const float* x    = (const float*)d_in[0];
    const float* t0   = (const float*)d_in[1];
    const float* t1   = (const float*)d_in[2];
    const float* bias = (const float*)d_in[3];
    float* out = (float*)d_out;

    cudaFuncSetAttribute(tn_kernel, cudaFuncAttributeMaxDynamicSharedMemorySize,
                         SMEM_BYTES);
    tn_kernel<<<GRID_X, NTHREADS, SMEM_BYTES>>>(x, t0, t1, bias, out);
}